// round 9
// baseline (speedup 1.0000x reference)
#include <cuda_runtime.h>
#include <cstdint>

#define B_  4096
#define T_  2048
#define HH  32
#define NGRP (B_ / 2)
typedef unsigned long long ull;

// ---------------- device globals ----------------
__device__ int g_next;
__device__ int g_order[B_];

// ---------------- helpers ----------------
__device__ __forceinline__ ull ffma2(ull a, ull b, ull c) {
    ull d;
    asm("fma.rn.f32x2 %0, %1, %2, %3;" : "=l"(d) : "l"(a), "l"(b), "l"(c));
    return d;
}
__device__ __forceinline__ ull pk2(float lo, float hi) {
    ull r;
    asm("mov.b64 %0, {%1, %2};" : "=l"(r) : "f"(lo), "f"(hi));
    return r;
}
__device__ __forceinline__ float2 unpk(ull v) {
    float2 r;
    asm("mov.b64 {%0, %1}, %2;" : "=f"(r.x), "=f"(r.y) : "l"(v));
    return r;
}
__device__ __forceinline__ float ex2a(float x) {
    float r; asm("ex2.approx.f32 %0, %1;" : "=f"(r) : "f"(x)); return r;
}
__device__ __forceinline__ float tanha(float x) {
    float r; asm("tanh.approx.f32 %0, %1;" : "=f"(r) : "f"(x)); return r;
}
#define LOG2E 1.4426950408889634f

// ---------------- single-block counting sort (desc length) + queue reset ----
__global__ void k_sort(const int* __restrict__ lengths) {
    __shared__ int cnt[T_];
    __shared__ int ps[1024];
    const int tid = threadIdx.x;

    cnt[tid] = 0;
    cnt[tid + 1024] = 0;
    if (tid == 0) g_next = 0;
    __syncthreads();

    for (int b = tid; b < B_; b += 1024)
        atomicAdd(&cnt[T_ - lengths[b]], 1);
    __syncthreads();

    int a = cnt[2 * tid], bb = cnt[2 * tid + 1];
    int s = a + bb;
    ps[tid] = s;
    __syncthreads();
    for (int d = 1; d < 1024; d <<= 1) {
        int v = (tid >= d) ? ps[tid - d] : 0;
        __syncthreads();
        ps[tid] += v;
        __syncthreads();
    }
    int excl = ps[tid] - s;
    cnt[2 * tid]     = excl;
    cnt[2 * tid + 1] = excl + a;
    __syncthreads();

    for (int b = tid; b < B_; b += 1024) {
        int pos = atomicAdd(&cnt[T_ - lengths[b]], 1);
        g_order[pos] = b;
    }
}

// ---------------- main kernel: one warp == TWO sequences, 3 warps/SMSP -----
// lane l owns h/c element l of both seqs; gate rows {l,32+l,64+l,96+l}.
// Weights in registers; i/f/o rows pre-scaled 0.5 (sigmoid=0.5*tanh(x/2)+0.5),
// g row raw. Smem: double-buffered h vectors (2 per warp).
__global__ __launch_bounds__(128, 3) void k_lstm(
    const float* __restrict__ x,      const int*   __restrict__ lengths,
    const float* __restrict__ w_ih,   const float* __restrict__ w_hh,
    const float* __restrict__ b_ih,   const float* __restrict__ b_hh,
    const float* __restrict__ fc_w,   const float* __restrict__ fc_b,
    const float* __restrict__ fc2_w,  const float* __restrict__ fc2_b,
    float* __restrict__ out)
{
    __shared__ __align__(16) float hs[2][4][2][HH];   // [buf][warp][seq][elem]

    const int lane = threadIdx.x & 31;
    const int wrp  = threadIdx.x >> 5;

    // ---- recurrent weights -> registers; i/f/o scaled 0.5, g raw ----
    ull w0[16], w1[16], w2[16], w3[16];
    float wih[4], bias[4];
    {
        const float2* r0 = reinterpret_cast<const float2*>(w_hh + (     lane) * 32);
        const float2* r1 = reinterpret_cast<const float2*>(w_hh + (32 + lane) * 32);
        const float2* r2 = reinterpret_cast<const float2*>(w_hh + (64 + lane) * 32);
        const float2* r3 = reinterpret_cast<const float2*>(w_hh + (96 + lane) * 32);
#pragma unroll
        for (int q = 0; q < 16; q++) {
            float2 t;
            t = __ldg(r0 + q); w0[q] = pk2(t.x * 0.5f, t.y * 0.5f);
            t = __ldg(r1 + q); w1[q] = pk2(t.x * 0.5f, t.y * 0.5f);
            t = __ldg(r2 + q); w2[q] = pk2(t.x,        t.y);
            t = __ldg(r3 + q); w3[q] = pk2(t.x * 0.5f, t.y * 0.5f);
        }
#pragma unroll
        for (int g = 0; g < 4; g++) {
            const float sc = (g == 2) ? 1.0f : 0.5f;
            const int j = 32 * g + lane;
            wih[g]  = w_ih[j] * sc;
            bias[g] = (b_ih[j] + b_hh[j]) * sc;
        }
    }

    for (;;) {
        int task = 0;
        if (lane == 0) task = atomicAdd(&g_next, 1);
        task = __shfl_sync(0xffffffffu, task, 0);
        if (task >= NGRP) break;

        const int sidA = g_order[2 * task];
        const int sidB = g_order[2 * task + 1];
        const int lenA = lengths[sidA];
        const int lenB = lengths[sidB];         // lenB <= lenA (desc sort)
        const int offA = sidA << 11;            // *T_ (2048)
        const int offB = sidB << 11;

        float cA = 0.0f, cB = 0.0f, hBo = 0.0f;
        hs[0][wrp][0][lane] = 0.0f; hs[0][wrp][1][lane] = 0.0f;
        hs[1][wrp][0][lane] = 0.0f; hs[1][wrp][1][lane] = 0.0f;
        __syncwarp();

        float xtA = __ldg(x + offA + lenA - 1);
        float xtB = __ldg(x + offB + lenB - 1);
        int pb = 0;

        for (int k = 0; k < lenA; ++k) {
            const int ixA = lenA - 2 - k, ixB = lenB - 2 - k;
            float xnA = (ixA >= 0) ? __ldg(x + offA + ixA) : 0.0f;
            float xnB = (ixB >= 0) ? __ldg(x + offB + ixB) : 0.0f;

            const ulonglong2* hpA =
                reinterpret_cast<const ulonglong2*>(hs[pb][wrp][0]);
            const ulonglong2* hpB =
                reinterpret_cast<const ulonglong2*>(hs[pb][wrp][1]);

            ull aA0 = pk2(fmaf(xtA, wih[0], bias[0]), 0.0f);
            ull aA1 = pk2(fmaf(xtA, wih[1], bias[1]), 0.0f);
            ull aA2 = pk2(fmaf(xtA, wih[2], bias[2]), 0.0f);
            ull aA3 = pk2(fmaf(xtA, wih[3], bias[3]), 0.0f);
            ull aB0 = pk2(fmaf(xtB, wih[0], bias[0]), 0.0f);
            ull aB1 = pk2(fmaf(xtB, wih[1], bias[1]), 0.0f);
            ull aB2 = pk2(fmaf(xtB, wih[2], bias[2]), 0.0f);
            ull aB3 = pk2(fmaf(xtB, wih[3], bias[3]), 0.0f);

#pragma unroll
            for (int q = 0; q < 8; q++) {
                ulonglong2 hA = hpA[q];              // broadcast LDS.128
                ulonglong2 hB = hpB[q];
                aA0 = ffma2(hA.x, w0[2 * q], aA0); aA0 = ffma2(hA.y, w0[2 * q + 1], aA0);
                aB0 = ffma2(hB.x, w0[2 * q], aB0); aB0 = ffma2(hB.y, w0[2 * q + 1], aB0);
                aA1 = ffma2(hA.x, w1[2 * q], aA1); aA1 = ffma2(hA.y, w1[2 * q + 1], aA1);
                aB1 = ffma2(hB.x, w1[2 * q], aB1); aB1 = ffma2(hB.y, w1[2 * q + 1], aB1);
                aA2 = ffma2(hA.x, w2[2 * q], aA2); aA2 = ffma2(hA.y, w2[2 * q + 1], aA2);
                aB2 = ffma2(hB.x, w2[2 * q], aB2); aB2 = ffma2(hB.y, w2[2 * q + 1], aB2);
                aA3 = ffma2(hA.x, w3[2 * q], aA3); aA3 = ffma2(hA.y, w3[2 * q + 1], aA3);
                aB3 = ffma2(hB.x, w3[2 * q], aB3); aB3 = ffma2(hB.y, w3[2 * q + 1], aB3);
            }

            const int npb = pb ^ 1;
            {   // seq A epilogue (always active: k < lenA)
                float2 f0 = unpk(aA0), f1 = unpk(aA1), f2 = unpk(aA2), f3 = unpk(aA3);
                float iv = fmaf(tanha(f0.x + f0.y), 0.5f, 0.5f);
                float fv = fmaf(tanha(f1.x + f1.y), 0.5f, 0.5f);
                float gv = tanha(f2.x + f2.y);
                float ov = fmaf(tanha(f3.x + f3.y), 0.5f, 0.5f);
                cA = fmaf(fv, cA, iv * gv);
                hs[npb][wrp][0][lane] = ov * tanha(cA);
            }
            {   // seq B epilogue (freeze after lenB)
                float2 f0 = unpk(aB0), f1 = unpk(aB1), f2 = unpk(aB2), f3 = unpk(aB3);
                float iv = fmaf(tanha(f0.x + f0.y), 0.5f, 0.5f);
                float fv = fmaf(tanha(f1.x + f1.y), 0.5f, 0.5f);
                float gv = tanha(f2.x + f2.y);
                float ov = fmaf(tanha(f3.x + f3.y), 0.5f, 0.5f);
                float cn = fmaf(fv, cB, iv * gv);
                float hn = ov * tanha(cn);
                if (k < lenB) { cB = cn; hBo = hn; }
                hs[npb][wrp][1][lane] = hBo;
            }
            pb = npb;
            __syncwarp();
            xtA = xnA; xtB = xnB;
        }

        // ---- MLP head for the 2 sequences ----
#pragma unroll 1
        for (int s = 0; s < 2; s++) {
            const float* hf = hs[pb][wrp][s];
            float y0 = fc_b[lane];
            float y1 = fc_b[lane + 32];
#pragma unroll
            for (int kk = 0; kk < 32; kk++) {
                float hk = hf[kk];
                y0 = fmaf(hk, __ldg(fc_w + lane * 32 + kk),        y0);
                y1 = fmaf(hk, __ldg(fc_w + (lane + 32) * 32 + kk), y1);
            }
            float e0 = (y0 > 0.0f) ? y0 : (ex2a(LOG2E * y0) - 1.0f);
            float e1 = (y1 > 0.0f) ? y1 : (ex2a(LOG2E * y1) - 1.0f);
            float p  = fmaf(e0, __ldg(fc2_w + lane),
                            e1 * __ldg(fc2_w + lane + 32));
#pragma unroll
            for (int off = 16; off; off >>= 1)
                p += __shfl_xor_sync(0xffffffffu, p, off);
            if (lane == 0)
                out[(s == 0) ? sidA : sidB] =
                    fmaf(tanha(0.5f * (p + fc2_b[0])), 0.5f, 0.5f);
        }
        __syncwarp();   // protect hs reuse by next task
    }
}

// ---------------- launch ----------------
extern "C" void kernel_launch(void* const* d_in, const int* in_sizes, int n_in,
                              void* d_out, int out_size)
{
    const float* x       = (const float*)d_in[0];
    const int*   lengths = (const int*)  d_in[1];
    const float* w_ih    = (const float*)d_in[2];
    const float* w_hh    = (const float*)d_in[3];
    const float* b_ih    = (const float*)d_in[4];
    const float* b_hh    = (const float*)d_in[5];
    const float* fc_w    = (const float*)d_in[6];
    const float* fc_b    = (const float*)d_in[7];
    const float* fc2_w   = (const float*)d_in[8];
    const float* fc2_b   = (const float*)d_in[9];
    float* out = (float*)d_out;

    k_sort<<<1, 1024>>>(lengths);
    k_lstm<<<148 * 3, 128>>>(x, lengths, w_ih, w_hh, b_ih, b_hh,
                             fc_w, fc_b, fc2_w, fc2_b, out);
}

// round 10
// speedup vs baseline: 1.1715x; 1.1715x over previous
#include <cuda_runtime.h>
#include <cstdint>

#define B_  4096
#define T_  2048
#define HH  32
typedef unsigned long long ull;

// ---------------- device globals ----------------
__device__ int g_next;
__device__ int g_order[B_];

// ---------------- helpers ----------------
__device__ __forceinline__ ull ffma2(ull a, ull b, ull c) {
    ull d;
    asm("fma.rn.f32x2 %0, %1, %2, %3;" : "=l"(d) : "l"(a), "l"(b), "l"(c));
    return d;
}
__device__ __forceinline__ ull add2(ull a, ull b) {
    ull d;
    asm("add.rn.f32x2 %0, %1, %2;" : "=l"(d) : "l"(a), "l"(b));
    return d;
}
__device__ __forceinline__ ull pk2(float lo, float hi) {
    ull r;
    asm("mov.b64 %0, {%1, %2};" : "=l"(r) : "f"(lo), "f"(hi));
    return r;
}
__device__ __forceinline__ float2 unpk(ull v) {
    float2 r;
    asm("mov.b64 {%0, %1}, %2;" : "=f"(r.x), "=f"(r.y) : "l"(v));
    return r;
}
__device__ __forceinline__ float ex2a(float x) {
    float r; asm("ex2.approx.f32 %0, %1;" : "=f"(r) : "f"(x)); return r;
}
__device__ __forceinline__ float tanha(float x) {
    float r; asm("tanh.approx.f32 %0, %1;" : "=f"(r) : "f"(x)); return r;
}
#define LOG2E 1.4426950408889634f

// ---------------- single-block counting sort (desc length) + queue reset ----
__global__ void k_sort(const int* __restrict__ lengths) {
    __shared__ int cnt[T_];
    __shared__ int ps[1024];
    const int tid = threadIdx.x;

    cnt[tid] = 0;
    cnt[tid + 1024] = 0;
    if (tid == 0) g_next = 0;
    __syncthreads();

    for (int b = tid; b < B_; b += 1024)
        atomicAdd(&cnt[T_ - lengths[b]], 1);
    __syncthreads();

    int a = cnt[2 * tid], bb = cnt[2 * tid + 1];
    int s = a + bb;
    ps[tid] = s;
    __syncthreads();
    for (int d = 1; d < 1024; d <<= 1) {
        int v = (tid >= d) ? ps[tid - d] : 0;
        __syncthreads();
        ps[tid] += v;
        __syncthreads();
    }
    int excl = ps[tid] - s;
    cnt[2 * tid]     = excl;
    cnt[2 * tid + 1] = excl + a;
    __syncthreads();

    for (int b = tid; b < B_; b += 1024) {
        int pos = atomicAdd(&cnt[T_ - lengths[b]], 1);
        g_order[pos] = b;
    }
}

// one LSTM step on gate accumulators -> updates c, writes h to hs[pb^1]
// i/f/o weights pre-scaled by 0.5 (sigmoid = 0.5*tanh(x/2)+0.5); g row raw.
// NOTE: no per-step __syncwarp — loop body is branch-free/convergent, and the
// STS -> next-step LDS pair aliases the same smem object so ptxas preserves
// order; LSU processes a warp's smem ops in issue order (double-buffered, so
// no same-step hazard).
#define LSTM_STEP(XT)                                                         \
    do {                                                                      \
        const ulonglong2* hp =                                                \
            reinterpret_cast<const ulonglong2*>(hs[pb][wrp]);                 \
        ull xp2 = pk2((XT), (XT));                                            \
        ull a0 = ffma2(xp2, wihp[0], biasp[0]), a0b = zero2;                  \
        ull a1 = ffma2(xp2, wihp[1], biasp[1]), a1b = zero2;                  \
        ull a2 = ffma2(xp2, wihp[2], biasp[2]), a2b = zero2;                  \
        ull a3 = ffma2(xp2, wihp[3], biasp[3]), a3b = zero2;                  \
        _Pragma("unroll")                                                     \
        for (int q = 0; q < 8; q++) {                                         \
            ulonglong2 h2 = hp[q];                                            \
            a0  = ffma2(h2.x, w0[2 * q],     a0);                             \
            a0b = ffma2(h2.y, w0[2 * q + 1], a0b);                            \
            a1  = ffma2(h2.x, w1[2 * q],     a1);                             \
            a1b = ffma2(h2.y, w1[2 * q + 1], a1b);                            \
            a2  = ffma2(h2.x, w2[2 * q],     a2);                             \
            a2b = ffma2(h2.y, w2[2 * q + 1], a2b);                            \
            a3  = ffma2(h2.x, w3[2 * q],     a3);                             \
            a3b = ffma2(h2.y, w3[2 * q + 1], a3b);                            \
        }                                                                     \
        float2 f0 = unpk(add2(a0, a0b));                                      \
        float2 f1 = unpk(add2(a1, a1b));                                      \
        float2 f2 = unpk(add2(a2, a2b));                                      \
        float2 f3 = unpk(add2(a3, a3b));                                      \
        float iv = fmaf(tanha(f0.x + f0.y), 0.5f, 0.5f);                      \
        float fv = fmaf(tanha(f1.x + f1.y), 0.5f, 0.5f);                      \
        float gv = tanha(f2.x + f2.y);                                        \
        float ov = fmaf(tanha(f3.x + f3.y), 0.5f, 0.5f);                      \
        c = fmaf(fv, c, iv * gv);                                             \
        float h = ov * tanha(c);                                              \
        pb ^= 1;                                                              \
        hs[pb][wrp][lane] = h;                                                \
    } while (0)

// ---------------- main kernel: one warp == one sequence, 3 warps/SMSP ------
__global__ __launch_bounds__(128, 3) void k_lstm(
    const float* __restrict__ x,      const int*   __restrict__ lengths,
    const float* __restrict__ w_ih,   const float* __restrict__ w_hh,
    const float* __restrict__ b_ih,   const float* __restrict__ b_hh,
    const float* __restrict__ fc_w,   const float* __restrict__ fc_b,
    const float* __restrict__ fc2_w,  const float* __restrict__ fc2_b,
    float* __restrict__ out)
{
    __shared__ __align__(16) float hs[2][4][HH];    // [buf][warp][elem]

    const int lane = threadIdx.x & 31;
    const int wrp  = threadIdx.x >> 5;
    const ull zero2 = pk2(0.0f, 0.0f);

    // ---- recurrent weights -> registers; i/f/o scaled 0.5, g raw ----
    ull w0[16], w1[16], w2[16], w3[16];
    ull wihp[4], biasp[4];
    {
        const float2* r0 = reinterpret_cast<const float2*>(w_hh + (     lane) * 32);
        const float2* r1 = reinterpret_cast<const float2*>(w_hh + (32 + lane) * 32);
        const float2* r2 = reinterpret_cast<const float2*>(w_hh + (64 + lane) * 32);
        const float2* r3 = reinterpret_cast<const float2*>(w_hh + (96 + lane) * 32);
#pragma unroll
        for (int q = 0; q < 16; q++) {
            float2 t;
            t = __ldg(r0 + q); w0[q] = pk2(t.x * 0.5f, t.y * 0.5f);
            t = __ldg(r1 + q); w1[q] = pk2(t.x * 0.5f, t.y * 0.5f);
            t = __ldg(r2 + q); w2[q] = pk2(t.x,        t.y);
            t = __ldg(r3 + q); w3[q] = pk2(t.x * 0.5f, t.y * 0.5f);
        }
#pragma unroll
        for (int g = 0; g < 4; g++) {
            const float sc = (g == 2) ? 1.0f : 0.5f;
            const int j = 32 * g + lane;
            wihp[g]  = pk2(w_ih[j] * sc, 0.0f);
            biasp[g] = pk2((b_ih[j] + b_hh[j]) * sc, 0.0f);
        }
    }

    for (;;) {
        int task = 0;
        if (lane == 0) task = atomicAdd(&g_next, 1);
        task = __shfl_sync(0xffffffffu, task, 0);
        if (task >= B_) break;

        const int b   = g_order[task];
        const int len = lengths[b];
        const float* xp = x + (long)b * T_;

        float c = 0.0f;
        hs[0][wrp][lane] = 0.0f;
        hs[1][wrp][lane] = 0.0f;
        __syncwarp();

        float xt = __ldg(xp + (len - 1));
        int pb = 0;

        // main loop: unconditional prefetch (t goes len-1 .. 1)
        for (int t = len - 1; t > 0; --t) {
            float xn = __ldg(xp + t - 1);
            LSTM_STEP(xt);
            xt = xn;
        }
        // peeled final step (t == 0)
        LSTM_STEP(xt);
        __syncwarp();   // make final h visible for the head reads

        // ---- MLP head ----
        const float* hf = hs[pb][wrp];
        float y0 = fc_b[lane];
        float y1 = fc_b[lane + 32];
#pragma unroll
        for (int k = 0; k < 32; k++) {
            float hk = hf[k];
            y0 = fmaf(hk, __ldg(fc_w + lane * 32 + k),        y0);
            y1 = fmaf(hk, __ldg(fc_w + (lane + 32) * 32 + k), y1);
        }
        float e0 = (y0 > 0.0f) ? y0 : (ex2a(LOG2E * y0) - 1.0f);
        float e1 = (y1 > 0.0f) ? y1 : (ex2a(LOG2E * y1) - 1.0f);
        float p  = fmaf(e0, __ldg(fc2_w + lane),
                        e1 * __ldg(fc2_w + lane + 32));
#pragma unroll
        for (int off = 16; off; off >>= 1)
            p += __shfl_xor_sync(0xffffffffu, p, off);
        if (lane == 0)
            out[b] = fmaf(tanha(0.5f * (p + fc2_b[0])), 0.5f, 0.5f);
        __syncwarp();   // protect hs reuse by next task
    }
}

// ---------------- launch ----------------
extern "C" void kernel_launch(void* const* d_in, const int* in_sizes, int n_in,
                              void* d_out, int out_size)
{
    const float* x       = (const float*)d_in[0];
    const int*   lengths = (const int*)  d_in[1];
    const float* w_ih    = (const float*)d_in[2];
    const float* w_hh    = (const float*)d_in[3];
    const float* b_ih    = (const float*)d_in[4];
    const float* b_hh    = (const float*)d_in[5];
    const float* fc_w    = (const float*)d_in[6];
    const float* fc_b    = (const float*)d_in[7];
    const float* fc2_w   = (const float*)d_in[8];
    const float* fc2_b   = (const float*)d_in[9];
    float* out = (float*)d_out;

    k_sort<<<1, 1024>>>(lengths);
    k_lstm<<<148 * 3, 128>>>(x, lengths, w_ih, w_hh, b_ih, b_hh,
                             fc_w, fc_b, fc2_w, fc2_b, out);
}